// round 12
// baseline (speedup 1.0000x reference)
#include <cuda_runtime.h>
#include <cuda_bf16.h>
#include <cstdint>

#define MROWS   512   // rows of weight / output dim
#define KDIM    20    // motion dim
#define OUT_DIM 512
#define TILE_M  128   // batch rows per tile
#define KPAD    64    // split-K layout: A=[hi20|lo20|hi20|0], B=[hi20|hi20|lo20|0]
#define GTHREADS 256  // 8 warps, each owns 64 output cols
#define SROW_W  36    // A smem row stride in words -> conflict-free LDSM phases
#define GRID_P  296   // persistent: 2 CTAs/SM

#define AW      (TILE_M * SROW_W)          // words per A buffer
#define SLAB_W  1024                        // words per epilogue slab (16x64)
// dyn smem: [A0 | A1 | 8 warps x 2 slabs]
#define SMEM_BYTES ((2 * AW + 8 * 2 * SLAB_W) * 4)

// B' table (bf16): g_Qbf[n*64 + k]; k 0-19 = Qhi, 20-39 = Qhi, 40-59 = Qlo, 60-63 = 0
__device__ __align__(16) __nv_bfloat16 g_Qbf[OUT_DIM * KPAD];

// ---------------------------------------------------------------------------
// helpers
// ---------------------------------------------------------------------------
__device__ __forceinline__ uint32_t bf2pack(float a, float b) {
    __nv_bfloat162 t = __floats2bfloat162_rn(a, b);
    return *reinterpret_cast<uint32_t*>(&t);
}

__device__ __forceinline__ float blockReduceSum(float x, float* red) {
    int lane = threadIdx.x & 31;
    int wid  = threadIdx.x >> 5;
    #pragma unroll
    for (int off = 16; off; off >>= 1) x += __shfl_xor_sync(0xffffffffu, x, off);
    if (lane == 0) red[wid] = x;
    __syncthreads();
    float s = (lane < 16) ? red[lane] : 0.f;
    #pragma unroll
    for (int off = 8; off; off >>= 1) s += __shfl_xor_sync(0xffffffffu, s, off);
    s = __shfl_sync(0xffffffffu, s, 0);
    __syncthreads();
    return s;
}

__device__ __forceinline__ void mma16816(float* d,
                                         uint32_t a0, uint32_t a1, uint32_t a2, uint32_t a3,
                                         uint32_t b0, uint32_t b1) {
    asm("mma.sync.aligned.m16n8k16.row.col.f32.bf16.bf16.f32 "
        "{%0,%1,%2,%3}, {%4,%5,%6,%7}, {%8,%9}, {%0,%1,%2,%3};"
        : "+f"(d[0]), "+f"(d[1]), "+f"(d[2]), "+f"(d[3])
        : "r"(a0), "r"(a1), "r"(a2), "r"(a3), "r"(b0), "r"(b1));
}

__device__ __forceinline__ void ldsm_x4(uint32_t* r, uint32_t addr) {
    asm volatile("ldmatrix.sync.aligned.m8n8.x4.shared.b16 {%0,%1,%2,%3}, [%4];"
                 : "=r"(r[0]), "=r"(r[1]), "=r"(r[2]), "=r"(r[3]) : "r"(addr));
}

__device__ __forceinline__ void stg_cs_v4(float* p, float4 v) {
    asm volatile("st.global.cs.v4.f32 [%0], {%1, %2, %3, %4};"
                 :: "l"(p), "f"(v.x), "f"(v.y), "f"(v.z), "f"(v.w) : "memory");
}

// ---------------------------------------------------------------------------
// Householder QR (LAPACK sgeqr2 + sorg2r) of W + 1e-8, W: [512,20].
// Emits bf16 hi/lo split table g_Qbf (B layout: [qh|qh|ql|0]).
// ---------------------------------------------------------------------------
__global__ void qr_kernel(const float* __restrict__ W) {
    __shared__ float sA[KDIM][MROWS];
    __shared__ float sV[MROWS];
    __shared__ float sTau[KDIM];
    __shared__ float sRed[16];

    const int t    = threadIdx.x;
    const int lane = t & 31;
    const int wid  = t >> 5;

    #pragma unroll
    for (int c = 0; c < KDIM; ++c)
        sA[c][t] = W[t * KDIM + c] + 1e-8f;
    __syncthreads();

    for (int j = 0; j < KDIM; ++j) {
        float a  = sA[j][t];
        float sq = (t > j) ? a * a : 0.f;
        float xnorm2 = blockReduceSum(sq, sRed);
        float alpha  = sA[j][j];
        float beta   = -copysignf(sqrtf(alpha * alpha + xnorm2), alpha);
        float tau    = (beta - alpha) / beta;
        float inv    = 1.f / (alpha - beta);
        float v      = (t == j) ? 1.f : ((t > j) ? a * inv : 0.f);
        sV[t] = v;
        if (t == j)      { sTau[j] = tau; sA[j][j] = beta; }
        else if (t > j)  { sA[j][t] = v; }
        __syncthreads();

        for (int c = j + 1 + wid; c < KDIM; c += 16) {
            float w = 0.f;
            #pragma unroll
            for (int i = lane; i < MROWS; i += 32) w += sV[i] * sA[c][i];
            #pragma unroll
            for (int off = 16; off; off >>= 1) w += __shfl_xor_sync(0xffffffffu, w, off);
            float tw = sTau[j] * w;
            #pragma unroll
            for (int i = lane; i < MROWS; i += 32) sA[c][i] -= tw * sV[i];
        }
        __syncthreads();
    }

    for (int j = KDIM - 1; j >= 0; --j) {
        float tau = sTau[j];
        float vt  = (t == j) ? 1.f : ((t > j) ? sA[j][t] : 0.f);
        sV[t] = vt;
        __syncthreads();

        for (int c = j + 1 + wid; c < KDIM; c += 16) {
            float w = 0.f;
            #pragma unroll
            for (int i = lane; i < MROWS; i += 32) w += sV[i] * sA[c][i];
            #pragma unroll
            for (int off = 16; off; off >>= 1) w += __shfl_xor_sync(0xffffffffu, w, off);
            float tw = tau * w;
            #pragma unroll
            for (int i = lane; i < MROWS; i += 32) sA[c][i] -= tw * sV[i];
        }
        __syncthreads();
        sA[j][t] = (t == j) ? (1.f - tau) : ((t > j) ? -tau * vt : 0.f);
        __syncthreads();
    }

    #pragma unroll
    for (int k = 0; k < KDIM; ++k) {
        float q = sA[k][t];
        __nv_bfloat16 h = __float2bfloat16_rn(q);
        float lo = q - __bfloat162float(h);
        g_Qbf[t * KPAD + k]            = h;
        g_Qbf[t * KPAD + KDIM + k]     = h;
        g_Qbf[t * KPAD + 2 * KDIM + k] = __float2bfloat16_rn(lo);
    }
    #pragma unroll
    for (int k = 3 * KDIM; k < KPAD; ++k)
        g_Qbf[t * KPAD + k] = __float2bfloat16_rn(0.f);
}

// ---------------------------------------------------------------------------
// Persistent HMMA GEMM: out[b][o] = sum_k input[b][k] * Q[o][k]
// R8 core (296 blocks, 128x512 tile, Bf register-resident, ldmatrix A frags)
// + double-buffered per-warp epilogue slabs: subtile ms stages d into
// slab[ms&1] while the PREVIOUS subtile's slab is read back and stored as
// fully-coalesced st.cs.v4 (4 wavefronts/instr). One pending store carried
// across tiles; drained once at kernel end.
// ---------------------------------------------------------------------------
__global__ void __launch_bounds__(GTHREADS, 2)
gemm_hmma_kernel(const float* __restrict__ input, float* __restrict__ out,
                 int batch, int ntiles) {
    extern __shared__ uint32_t dynsmem[];
    uint32_t* sW0  = dynsmem;
    uint32_t* sW1  = dynsmem + AW;
    uint32_t* sEpi = dynsmem + 2 * AW;

    const int tid  = threadIdx.x;
    const int wid  = tid >> 5;
    const int lane = tid & 31;
    const int g    = lane >> 2;        // fragment row group 0..7
    const int cq   = lane & 3;         // quad col: k pair base = 2*cq

    // ---- B fragments (once per block) ----
    uint32_t Bf[8][8];
    {
        const uint32_t* qw = reinterpret_cast<const uint32_t*>(g_Qbf);
        const int nb = wid * 64 + g;
        #pragma unroll
        for (int j = 0; j < 8; ++j) {
            const uint32_t* qrow = qw + (nb + 8 * j) * (KPAD / 2) + cq;
            #pragma unroll
            for (int t = 0; t < 8; ++t)
                Bf[j][t] = qrow[4 * t];
        }
    }

    // ---- conversion: tile tt -> buffer buf ----
    auto convert_tile = [&](long long tt, int buf) {
        const int r = tid >> 1;                 // row 0..127
        const int h = tid & 1;                  // half: k0 = 10h
        const long long grow = tt * TILE_M + r;
        float2 v[5];
        if (grow < batch) {
            const float2* src = reinterpret_cast<const float2*>(input + grow * KDIM + 10 * h);
            #pragma unroll
            for (int p = 0; p < 5; ++p) v[p] = src[p];
        } else {
            #pragma unroll
            for (int p = 0; p < 5; ++p) v[p] = make_float2(0.f, 0.f);
        }
        uint32_t* row = (buf ? sW1 : sW0) + r * SROW_W;
        #pragma unroll
        for (int p = 0; p < 5; ++p) {
            const int k = 10 * h + 2 * p;
            float x0 = v[p].x, x1 = v[p].y;
            __nv_bfloat16 h0 = __float2bfloat16_rn(x0);
            __nv_bfloat16 h1 = __float2bfloat16_rn(x1);
            uint32_t hp = bf2pack(x0, x1);
            uint32_t lp = bf2pack(x0 - __bfloat162float(h0), x1 - __bfloat162float(h1));
            row[k / 2]      = hp;   // hi block
            row[10 + k / 2] = lp;   // lo block
            row[20 + k / 2] = hp;   // hi dup
        }
        if (h) { row[30] = 0u; row[31] = 0u; }   // k 60..63 = 0
    };

    // ldmatrix lane address base
    const uint32_t smem0 = (uint32_t)__cvta_generic_to_shared(sW0);
    const uint32_t smem1 = (uint32_t)__cvta_generic_to_shared(sW1);
    const uint32_t lane_off = (((lane & 15) * SROW_W + ((lane & 16) ? 4 : 0)) * 4);

    // per-warp slabs: 2 x (16 rows x 64 words)
    uint32_t* slab0 = sEpi + wid * (2 * SLAB_W);
    uint32_t* slab1 = slab0 + SLAB_W;
    const int erow2  = lane >> 4;       // 0/1 (read phase)
    const int echunk = lane & 15;       // 16B chunk (read phase)

    // coalesced read-back + streaming v4 stores of a staged subtile
    auto store_slab = [&](uint32_t* slab, long long rowbase) {
        #pragma unroll
        for (int p = 0; p < 8; ++p) {
            const int row = 2 * p + erow2;
            const int sw  = (row & 3) * 8;
            float4 v = *reinterpret_cast<float4*>(slab + row * 64 + ((echunk * 4) ^ sw));
            const long long grow = rowbase + row;
            if (grow < batch)
                stg_cs_v4(out + grow * OUT_DIM + wid * 64 + echunk * 4, v);
        }
    };

    const long long stride = gridDim.x;
    const long long t0 = blockIdx.x;

    if (t0 < ntiles) convert_tile(t0, 0);
    __syncthreads();

    long long pend_rowbase = -1;        // pending staged subtile (slab index = pend_slab)
    uint32_t* pend_slab = slab1;        // ms=7 of previous tile lands in slab1
    int buf = 0;

    for (long long t = t0; t < ntiles; t += stride) {
        const long long tn = t + stride;
        if (tn < ntiles) convert_tile(tn, buf ^ 1);

        const long long tb = t * TILE_M;
        const uint32_t sbase = (buf ? smem1 : smem0) + lane_off;

        #pragma unroll 1
        for (int ms = 0; ms < 8; ++ms) {
            const uint32_t mbase = sbase + (uint32_t)(16 * ms * SROW_W * 4);
            uint32_t* cur = (ms & 1) ? slab1 : slab0;

            float acc[8][4];
            #pragma unroll
            for (int j = 0; j < 8; ++j)
                acc[j][0] = acc[j][1] = acc[j][2] = acc[j][3] = 0.f;

            #pragma unroll
            for (int s = 0; s < 4; ++s) {
                uint32_t a[4];
                ldsm_x4(a, mbase + 32u * s);
                #pragma unroll
                for (int j = 0; j < 8; ++j)
                    mma16816(acc[j], a[0], a[1], a[2], a[3],
                             Bf[j][2 * s], Bf[j][2 * s + 1]);
            }

            // order: prior LDS of 'cur' (2 subtiles ago) done; STS of pending visible
            __syncwarp();

            // stage current subtile into cur slab (xor swizzle: 2-phase STS.64)
            #pragma unroll
            for (int rr = 0; rr < 2; ++rr) {
                const int row  = g + 8 * rr;
                const int sw   = (row & 3) * 8;
                uint32_t* base = cur + row * 64;
                #pragma unroll
                for (int j = 0; j < 8; ++j) {
                    const int col = 8 * j + 2 * cq;
                    *reinterpret_cast<float2*>(base + (col ^ sw)) =
                        make_float2(acc[j][2 * rr], acc[j][2 * rr + 1]);
                }
            }

            // drain PREVIOUS subtile (other slab) — overlaps next MMA work
            if (pend_rowbase >= 0)
                store_slab(pend_slab, pend_rowbase);
            pend_slab    = cur;
            pend_rowbase = tb + 16 * ms;
        }

        __syncthreads();   // A next buffer fully written; old A buffer free
        buf ^= 1;
    }

    // final drain
    __syncwarp();
    if (pend_rowbase >= 0)
        store_slab(pend_slab, pend_rowbase);
}

// ---------------------------------------------------------------------------
extern "C" void kernel_launch(void* const* d_in, const int* in_sizes, int n_in,
                              void* d_out, int out_size) {
    const float* input  = (const float*)d_in[0];
    const float* weight = (const float*)d_in[1];
    int s0 = in_sizes[0], s1 = in_sizes[1];
    if (s0 < s1) {
        const float* tmp = input; input = weight; weight = tmp;
        int ts = s0; s0 = s1; s1 = ts;
    }
    const int batch  = s0 / KDIM;
    const int ntiles = (batch + TILE_M - 1) / TILE_M;

    cudaFuncSetAttribute(gemm_hmma_kernel,
                         cudaFuncAttributeMaxDynamicSharedMemorySize, SMEM_BYTES);

    qr_kernel<<<1, MROWS>>>(weight);
    gemm_hmma_kernel<<<GRID_P, GTHREADS, SMEM_BYTES>>>(input, (float*)d_out, batch, ntiles);
}

// round 13
// speedup vs baseline: 1.1126x; 1.1126x over previous
#include <cuda_runtime.h>
#include <cuda_bf16.h>
#include <cstdint>

#define MROWS   512   // rows of weight / output dim
#define KDIM    20    // motion dim
#define OUT_DIM 512
#define TILE_M  128   // batch rows per tile
#define KPAD    64    // split-K layout: A=[hi20|lo20|hi20|0], B=[hi20|hi20|lo20|0]
#define GTHREADS 256  // 8 warps, each owns 64 output cols
#define SROW_W  36    // A smem row stride in words -> conflict-free LDSM phases
#define GRID_P  296   // persistent: 2 CTAs/SM

// B' table (bf16): g_Qbf[n*64 + k]; k 0-19 = Qhi, 20-39 = Qhi, 40-59 = Qlo, 60-63 = 0
__device__ __align__(16) __nv_bfloat16 g_Qbf[OUT_DIM * KPAD];

// ---------------------------------------------------------------------------
// helpers
// ---------------------------------------------------------------------------
__device__ __forceinline__ uint32_t bf2pack(float a, float b) {
    __nv_bfloat162 t = __floats2bfloat162_rn(a, b);
    return *reinterpret_cast<uint32_t*>(&t);
}

__device__ __forceinline__ float blockReduceSum(float x, float* red) {
    int lane = threadIdx.x & 31;
    int wid  = threadIdx.x >> 5;
    #pragma unroll
    for (int off = 16; off; off >>= 1) x += __shfl_xor_sync(0xffffffffu, x, off);
    if (lane == 0) red[wid] = x;
    __syncthreads();
    float s = (lane < 16) ? red[lane] : 0.f;
    #pragma unroll
    for (int off = 8; off; off >>= 1) s += __shfl_xor_sync(0xffffffffu, s, off);
    s = __shfl_sync(0xffffffffu, s, 0);
    __syncthreads();
    return s;
}

__device__ __forceinline__ void mma16816(float* d,
                                         uint32_t a0, uint32_t a1, uint32_t a2, uint32_t a3,
                                         uint32_t b0, uint32_t b1) {
    asm("mma.sync.aligned.m16n8k16.row.col.f32.bf16.bf16.f32 "
        "{%0,%1,%2,%3}, {%4,%5,%6,%7}, {%8,%9}, {%0,%1,%2,%3};"
        : "+f"(d[0]), "+f"(d[1]), "+f"(d[2]), "+f"(d[3])
        : "r"(a0), "r"(a1), "r"(a2), "r"(a3), "r"(b0), "r"(b1));
}

__device__ __forceinline__ void ldsm_x4(uint32_t* r, uint32_t addr) {
    asm volatile("ldmatrix.sync.aligned.m8n8.x4.shared.b16 {%0,%1,%2,%3}, [%4];"
                 : "=r"(r[0]), "=r"(r[1]), "=r"(r[2]), "=r"(r[3]) : "r"(addr));
}

__device__ __forceinline__ void stg_cs_v2(float* p, float x, float y) {
    asm volatile("st.global.cs.v2.f32 [%0], {%1, %2};" :: "l"(p), "f"(x), "f"(y) : "memory");
}

// ---------------------------------------------------------------------------
// QR of W + 1e-8 (W: [512,20]) with LAPACK geqr2 signs, but WITHOUT org2r:
//   1. geqr2 -> R (upper 20x20, LAPACK sign convention)   [20 serial iters]
//   2. Rinv  (20 parallel back-substitutions)
//   3. Q = (W + 1e-8) * Rinv  (512 independent rows)      [fully parallel]
// Emits bf16 hi/lo split table g_Qbf (B layout: [qh|qh|ql|0]).
// ---------------------------------------------------------------------------
__global__ void qr_kernel(const float* __restrict__ W) {
    __shared__ float sA[KDIM][MROWS];    // column-major: sA[c][t] = A[t][c]
    __shared__ float sV[MROWS];
    __shared__ float sRinv[KDIM][KDIM + 1];
    __shared__ float sRed[16];

    const int t    = threadIdx.x;
    const int lane = t & 31;
    const int wid  = t >> 5;

    float wrow[KDIM];                    // this thread's row of W + 1e-8
    #pragma unroll
    for (int c = 0; c < KDIM; ++c) {
        wrow[c] = W[t * KDIM + c] + 1e-8f;
        sA[c][t] = wrow[c];
    }
    __syncthreads();

    float tau_cur;                       // broadcast within iter

    // ---- geqr2: reduce to R (keep only the triangle; reflectors transient) ----
    for (int j = 0; j < KDIM; ++j) {
        float a  = sA[j][t];
        float sq = (t > j) ? a * a : 0.f;
        float xnorm2 = blockReduceSum(sq, sRed);
        float alpha  = sA[j][j];
        float beta   = -copysignf(sqrtf(alpha * alpha + xnorm2), alpha);  // LAPACK sign
        tau_cur      = (beta - alpha) / beta;
        float inv    = 1.f / (alpha - beta);
        float v      = (t == j) ? 1.f : ((t > j) ? a * inv : 0.f);
        sV[t] = v;
        if (t == j) sA[j][j] = beta;     // R diagonal
        __syncthreads();

        // trailing update: one warp per column
        for (int c = j + 1 + wid; c < KDIM; c += 16) {
            float w = 0.f;
            #pragma unroll
            for (int i = lane; i < MROWS; i += 32) w += sV[i] * sA[c][i];
            #pragma unroll
            for (int off = 16; off; off >>= 1) w += __shfl_xor_sync(0xffffffffu, w, off);
            float tw = tau_cur * w;
            #pragma unroll
            for (int i = lane; i < MROWS; i += 32) sA[c][i] -= tw * sV[i];
        }
        __syncthreads();
    }

    // ---- Rinv: thread c solves R x = e_c by back-substitution ----
    // R[r][c] = sA[c][r] (r <= c)
    if (t < KDIM) {
        const int c = t;
        float x[KDIM];
        #pragma unroll
        for (int i = 0; i < KDIM; ++i) x[i] = 0.f;
        x[c] = 1.f / sA[c][c];
        for (int i = c - 1; i >= 0; --i) {
            float s = 0.f;
            for (int k = i + 1; k <= c; ++k) s += sA[k][i] * x[k];   // R[i][k]*x[k]
            x[i] = -s / sA[i][i];
        }
        #pragma unroll
        for (int k = 0; k < KDIM; ++k) sRinv[k][c] = x[k];
    }
    __syncthreads();

    // ---- Q row t = wrow * Rinv;  bf16 hi/lo split -> g_Qbf ----
    #pragma unroll
    for (int c = 0; c < KDIM; ++c) {
        float q = 0.f;
        for (int k = 0; k <= c; ++k) q += wrow[k] * sRinv[k][c];    // Rinv upper-tri
        __nv_bfloat16 h = __float2bfloat16_rn(q);
        float lo = q - __bfloat162float(h);
        g_Qbf[t * KPAD + c]            = h;
        g_Qbf[t * KPAD + KDIM + c]     = h;
        g_Qbf[t * KPAD + 2 * KDIM + c] = __float2bfloat16_rn(lo);
    }
    #pragma unroll
    for (int k = 3 * KDIM; k < KPAD; ++k)
        g_Qbf[t * KPAD + k] = __float2bfloat16_rn(0.f);
}

// ---------------------------------------------------------------------------
// Persistent HMMA GEMM (R8, unchanged — known best): out = input @ Q^T.
// 296 blocks grid-stride over M tiles. B fragments register-resident (once
// per block). A tiles double-buffered; A fragments via ldmatrix.x4; scattered
// st.global.cs.v2 (full 32B sectors; L1-wavefront-optimal for this layout).
// ---------------------------------------------------------------------------
__global__ void __launch_bounds__(GTHREADS, 2)
gemm_hmma_kernel(const float* __restrict__ input, float* __restrict__ out,
                 int batch, int ntiles) {
    __shared__ uint32_t sW[2][TILE_M * SROW_W];   // 2 x 18432 B

    const int tid  = threadIdx.x;
    const int wid  = tid >> 5;
    const int lane = tid & 31;
    const int g    = lane >> 2;        // fragment row group 0..7
    const int cq   = lane & 3;         // quad col: k pair base = 2*cq

    // ---- B fragments (once per block): B[j][t] = (B'[2cq+8t, n], B'[+1, n]) ----
    uint32_t Bf[8][8];
    {
        const uint32_t* qw = reinterpret_cast<const uint32_t*>(g_Qbf);
        const int nb = wid * 64 + g;
        #pragma unroll
        for (int j = 0; j < 8; ++j) {
            const uint32_t* qrow = qw + (nb + 8 * j) * (KPAD / 2) + cq;
            #pragma unroll
            for (int t = 0; t < 8; ++t)
                Bf[j][t] = qrow[4 * t];
        }
    }

    // ---- conversion: tile tt -> buffer buf ----
    auto convert_tile = [&](long long tt, int buf) {
        const int r = tid >> 1;                 // row 0..127
        const int h = tid & 1;                  // half: k0 = 10h
        const long long grow = tt * TILE_M + r;
        float2 v[5];
        if (grow < batch) {
            const float2* src = reinterpret_cast<const float2*>(input + grow * KDIM + 10 * h);
            #pragma unroll
            for (int p = 0; p < 5; ++p) v[p] = src[p];
        } else {
            #pragma unroll
            for (int p = 0; p < 5; ++p) v[p] = make_float2(0.f, 0.f);
        }
        uint32_t* row = sW[buf] + r * SROW_W;
        #pragma unroll
        for (int p = 0; p < 5; ++p) {
            const int k = 10 * h + 2 * p;
            float x0 = v[p].x, x1 = v[p].y;
            __nv_bfloat16 h0 = __float2bfloat16_rn(x0);
            __nv_bfloat16 h1 = __float2bfloat16_rn(x1);
            uint32_t hp = bf2pack(x0, x1);
            uint32_t lp = bf2pack(x0 - __bfloat162float(h0), x1 - __bfloat162float(h1));
            row[k / 2]      = hp;   // hi block
            row[10 + k / 2] = lp;   // lo block
            row[20 + k / 2] = hp;   // hi dup
        }
        if (h) { row[30] = 0u; row[31] = 0u; }   // k 60..63 = 0
    };

    // ldmatrix lane address base: row = (lane&15), k-half = (lane&16)?words 4..7
    const uint32_t smem0 = (uint32_t)__cvta_generic_to_shared(&sW[0][0]);
    const uint32_t smem1 = (uint32_t)__cvta_generic_to_shared(&sW[1][0]);
    const uint32_t lane_off = (((lane & 15) * SROW_W + ((lane & 16) ? 4 : 0)) * 4);

    const int colbase = wid * 64 + 2 * cq;
    const long long stride = gridDim.x;
    const long long t0 = blockIdx.x;

    if (t0 < ntiles) convert_tile(t0, 0);
    __syncthreads();

    int buf = 0;
    for (long long t = t0; t < ntiles; t += stride) {
        // prefetch-convert next tile into the other buffer (overlaps MMAs below)
        const long long tn = t + stride;
        if (tn < ntiles) convert_tile(tn, buf ^ 1);

        const long long tb = t * TILE_M;
        const uint32_t sbase = (buf ? smem1 : smem0) + lane_off;

        #pragma unroll 1
        for (int ms = 0; ms < 8; ++ms) {
            const uint32_t mbase = sbase + (uint32_t)(16 * ms * SROW_W * 4);

            float acc[8][4];
            #pragma unroll
            for (int j = 0; j < 8; ++j)
                acc[j][0] = acc[j][1] = acc[j][2] = acc[j][3] = 0.f;

            #pragma unroll
            for (int s = 0; s < 4; ++s) {
                uint32_t a[4];
                ldsm_x4(a, mbase + 32u * s);   // 8 words per k16 chunk
                #pragma unroll
                for (int j = 0; j < 8; ++j)
                    mma16816(acc[j], a[0], a[1], a[2], a[3],
                             Bf[j][2 * s], Bf[j][2 * s + 1]);
            }

            const long long grow0 = tb + 16 * ms + g;
            if (grow0 < batch) {
                float* p0 = out + grow0 * OUT_DIM + colbase;
                #pragma unroll
                for (int j = 0; j < 8; ++j)
                    stg_cs_v2(p0 + 8 * j, acc[j][0], acc[j][1]);
            }
            if (grow0 + 8 < batch) {
                float* p1 = out + (grow0 + 8) * OUT_DIM + colbase;
                #pragma unroll
                for (int j = 0; j < 8; ++j)
                    stg_cs_v2(p1 + 8 * j, acc[j][2], acc[j][3]);
            }
        }

        __syncthreads();   // next buffer fully written; old buffer free
        buf ^= 1;
    }
}

// ---------------------------------------------------------------------------
extern "C" void kernel_launch(void* const* d_in, const int* in_sizes, int n_in,
                              void* d_out, int out_size) {
    const float* input  = (const float*)d_in[0];
    const float* weight = (const float*)d_in[1];
    int s0 = in_sizes[0], s1 = in_sizes[1];
    if (s0 < s1) {
        const float* tmp = input; input = weight; weight = tmp;
        int ts = s0; s0 = s1; s1 = ts;
    }
    const int batch  = s0 / KDIM;
    const int ntiles = (batch + TILE_M - 1) / TILE_M;

    qr_kernel<<<1, MROWS>>>(weight);
    gemm_hmma_kernel<<<GRID_P, GTHREADS>>>(input, (float*)d_out, batch, ntiles);
}